// round 8
// baseline (speedup 1.0000x reference)
#include <cuda_runtime.h>
#include <cuda_bf16.h>
#include <cstdint>

// ---------------------------------------------------------------------------
// Persistent-per-CTA causal generator, register-chained GEMMs, 32-row warps.
// BM=256 rows/CTA, 8 warps, each warp owns 32 rows x all 128 cols.
// B fragments (A_i / W1 / W2 panels) are loaded once per k-step per warp and
// reused across BOTH 16-row m-tiles -> per-row smem crossbar traffic halves
// vs the 16-row version. h1/h2 stay entirely in registers via the C->A
// fragment identity. One __syncthreads per step.
// ---------------------------------------------------------------------------

#define XD 64
#define HD 128
#define BB 65536
#define BM 256
#define NT 256

// smem byte offsets. bf16 panels: 128B rows, SW128 swizzled.
#define OFF_X    0u         // X bf16 [256][64]                   32768
#define OFF_A    32768u     // A_i: 2 bufs x 2 panels [64][64]    32768
#define OFF_W1   65536u     // Ws1^T: 2 N-panels [128][64]        32768
#define OFF_W2   98304u     //                                    32768
#define OFF_Z    131072u    // zT fp32 [64][260]                  66560
#define OFF_VEC  197632u    // 2 bufs x (Wz[128],bi[128],wf[128]) 3072
#define OFF_B1   200704u    // fp32[128]
#define OFF_B2   201216u    // fp32[128]
#define OFF_BF   201728u    // fp32[64]
#define SMEM_BYTES 201984u

#define ZSTRIDE 260

__device__ __nv_bfloat16 g_A[XD * XD * HD];   // [step][k][n], mask folded in
__device__ __nv_bfloat16 g_W1[HD * HD];       // [k][n] = Ws1[n][k]
__device__ __nv_bfloat16 g_W2[HD * HD];       // [k][n] = Ws2[n][k]

__device__ __forceinline__ unsigned swz(unsigned off) {
    return off ^ ((off >> 3) & 0x70u);
}
__device__ __forceinline__ void ldsm4(unsigned addr, unsigned &r0, unsigned &r1,
                                      unsigned &r2, unsigned &r3) {
    asm volatile("ldmatrix.sync.aligned.m8n8.x4.shared.b16 {%0,%1,%2,%3}, [%4];"
                 : "=r"(r0), "=r"(r1), "=r"(r2), "=r"(r3) : "r"(addr));
}
__device__ __forceinline__ void ldsm4t(unsigned addr, unsigned &r0, unsigned &r1,
                                       unsigned &r2, unsigned &r3) {
    asm volatile("ldmatrix.sync.aligned.m8n8.x4.trans.shared.b16 {%0,%1,%2,%3}, [%4];"
                 : "=r"(r0), "=r"(r1), "=r"(r2), "=r"(r3) : "r"(addr));
}
__device__ __forceinline__ void mma16816(float *c, unsigned a0, unsigned a1,
                                         unsigned a2, unsigned a3,
                                         unsigned b0, unsigned b1) {
    asm volatile(
        "mma.sync.aligned.m16n8k16.row.col.f32.bf16.bf16.f32 "
        "{%0,%1,%2,%3}, {%4,%5,%6,%7}, {%8,%9}, {%0,%1,%2,%3};"
        : "+f"(c[0]), "+f"(c[1]), "+f"(c[2]), "+f"(c[3])
        : "r"(a0), "r"(a1), "r"(a2), "r"(a3), "r"(b0), "r"(b1));
}
__device__ __forceinline__ unsigned packbf(float lo, float hi) {
    __nv_bfloat162 t = __floats2bfloat162_rn(lo, hi);
    return *(unsigned *)&t;
}
__device__ __forceinline__ void cp16(unsigned saddr, const void *g) {
    asm volatile("cp.async.cg.shared.global [%0], [%1], 16;" ::"r"(saddr), "l"(g));
}
__device__ __forceinline__ void cp4(unsigned saddr, const void *g) {
    asm volatile("cp.async.ca.shared.global [%0], [%1], 4;" ::"r"(saddr), "l"(g));
}

__device__ __forceinline__ void prefetch_step(int j, unsigned sbase, int tid,
                                              const float *Wi, const float *bi,
                                              const float *wf) {
    const int b = j & 1;
    unsigned abase = sbase + OFF_A + (unsigned)b * 16384u;
    const char *gA = (const char *)g_A + (size_t)j * 16384;
#pragma unroll
    for (int c = tid; c < 1024; c += NT) {
        int row = c >> 4, nc = c & 15;
        unsigned off = (unsigned)(nc >> 3) * 8192u +
                       swz((unsigned)(row * 128 + (nc & 7) * 16));
        cp16(abase + off, gA + c * 16);
    }
    unsigned vbase = sbase + OFF_VEC + (unsigned)b * 1536u;
    if (tid < 128) {
        cp4(vbase + tid * 4, Wi + ((size_t)j * HD + tid) * (XD + 1) + XD);
    } else if (tid < 160) {
        int t = tid - 128;
        cp16(vbase + 512 + t * 16, bi + j * HD + t * 4);
    } else if (tid < 192) {
        int t = tid - 160;
        cp16(vbase + 1024 + t * 16, wf + j * HD + t * 4);
    }
}

__global__ void __launch_bounds__(NT, 1)
gen_kernel(const float *__restrict__ x, const float *__restrict__ z,
           const float *__restrict__ Wi, const float *__restrict__ bi,
           const float *__restrict__ bs1, const float *__restrict__ bs2,
           const float *__restrict__ wf, const float *__restrict__ bfp,
           float *__restrict__ out) {
    extern __shared__ char smem[];
    const int tid  = threadIdx.x;
    const int lane = tid & 31;
    const int warp = tid >> 5;
    const int mb   = warp * 32;        // 8 warps x 32 rows = 256 rows
    const int R0   = blockIdx.x * BM;
    const unsigned sbase  = (unsigned)__cvta_generic_to_shared(smem);
    const unsigned half16 = (lane & 16) ? 16u : 0u;
    const unsigned klane  = (unsigned)(lane & 15);

    float *sZT = (float *)(smem + OFF_Z);
    float *sB1 = (float *)(smem + OFF_B1);
    float *sB2 = (float *)(smem + OFF_B2);
    float *sBF = (float *)(smem + OFF_BF);

    // ---------------- prologue: resident loads ----------------
#pragma unroll
    for (int c = tid; c < BM * XD / 4; c += NT) {
        int row = c >> 4, f4 = c & 15;
        float4 v = *(const float4 *)(x + (size_t)(R0 + row) * XD + f4 * 4);
        __nv_bfloat162 p0 = __floats2bfloat162_rn(v.x, v.y);
        __nv_bfloat162 p1 = __floats2bfloat162_rn(v.z, v.w);
        unsigned off = swz((unsigned)(row * 128 + f4 * 8));
        uint2 u;
        u.x = *(unsigned *)&p0;
        u.y = *(unsigned *)&p1;
        *(uint2 *)(smem + OFF_X + off) = u;
    }
#pragma unroll
    for (int idx = tid; idx < BM * XD; idx += NT) {
        int row = idx & 255, c = idx >> 8;
#pragma unroll
        for (int cc = 0; cc < XD / (BM * XD / (BM * XD)); cc += 100000) {}
        sZT[c * ZSTRIDE + row] = z[(size_t)(R0 + row) * XD + c];
    }
    {
        const uint4 *gW1 = (const uint4 *)g_W1;
        const uint4 *gW2 = (const uint4 *)g_W2;
#pragma unroll
        for (int c = tid; c < 2048; c += NT) {
            int row = c >> 4, nc = c & 15;
            unsigned off = (unsigned)(nc >> 3) * 16384u +
                           swz((unsigned)(row * 128 + (nc & 7) * 16));
            *(uint4 *)(smem + OFF_W1 + off) = gW1[c];
            *(uint4 *)(smem + OFF_W2 + off) = gW2[c];
        }
    }
    if (tid < HD) {
        sB1[tid] = bs1[tid];
        sB2[tid] = bs2[tid];
        if (tid < XD) sBF[tid] = bfp[tid];
    }
    prefetch_step(0, sbase, tid, Wi, bi, wf);
    asm volatile("cp.async.commit_group;" ::: "memory");

    float acc[2][16][4];     // [m-tile][n-tile][frag]
    unsigned af[2][8][4];    // h as A-fragments  [m-tile][k-block][frag]

    // ---------------- 64 sequential steps, ONE barrier each ----------------
    for (int i = 0; i < XD; i++) {
        const int vb = i & 1;
        const float *sWz = (float *)(smem + OFF_VEC + vb * 1536u);
        const float *sBi = sWz + 128;
        const float *sWf = sWz + 256;

        asm volatile("cp.async.wait_group 0;" ::: "memory");
        __syncthreads();   // A_i/vec_i visible; X col i-1 visible

        if (i + 1 < XD) prefetch_step(i + 1, sbase, tid, Wi, bi, wf);
        asm volatile("cp.async.commit_group;" ::: "memory");

        // ---- GEMM1: [32x128] = X[32x64] @ A_i[64x128] ----
#pragma unroll
        for (int mt = 0; mt < 2; mt++)
#pragma unroll
            for (int nt = 0; nt < 16; nt++) {
                acc[mt][nt][0] = 0.f; acc[mt][nt][1] = 0.f;
                acc[mt][nt][2] = 0.f; acc[mt][nt][3] = 0.f;
            }
#pragma unroll
        for (int kb = 0; kb < 4; kb++) {
            unsigned a[2][4];
#pragma unroll
            for (int mt = 0; mt < 2; mt++) {
                unsigned arow = (unsigned)(mb + mt * 16 + (lane & 15));
                unsigned aaddr = sbase + OFF_X +
                                 swz(arow * 128u + (unsigned)kb * 32u + half16);
                ldsm4(aaddr, a[mt][0], a[mt][1], a[mt][2], a[mt][3]);
            }
            unsigned brow = (unsigned)kb * 16u + klane;
            unsigned bbase = sbase + OFF_A + (unsigned)vb * 16384u;
#pragma unroll
            for (int ntp = 0; ntp < 8; ntp++) {
                unsigned b0, b1, b2, b3;
                unsigned baddr = bbase + (unsigned)(ntp >> 2) * 8192u +
                                 swz(brow * 128u + (unsigned)(ntp & 3) * 32u + half16);
                ldsm4t(baddr, b0, b1, b2, b3);
#pragma unroll
                for (int mt = 0; mt < 2; mt++) {
                    mma16816(acc[mt][2 * ntp],     a[mt][0], a[mt][1], a[mt][2], a[mt][3], b0, b1);
                    mma16816(acc[mt][2 * ntp + 1], a[mt][0], a[mt][1], a[mt][2], a[mt][3], b2, b3);
                }
            }
        }
        // epilogue 1: relu(acc + z*Wz + bi) -> A-fragments (registers)
#pragma unroll
        for (int mt = 0; mt < 2; mt++) {
            const int r0 = mb + mt * 16 + (lane >> 2), r1 = r0 + 8;
            const float z0 = sZT[i * ZSTRIDE + r0];
            const float z1 = sZT[i * ZSTRIDE + r1];
#pragma unroll
            for (int kb = 0; kb < 8; kb++) {
#pragma unroll
                for (int t = 0; t < 2; t++) {
                    float *a = acc[mt][2 * kb + t];
                    int c0 = (2 * kb + t) * 8 + 2 * (lane & 3);
                    float wz0 = sWz[c0], wz1 = sWz[c0 + 1];
                    float b0 = sBi[c0], b1 = sBi[c0 + 1];
                    float v00 = fmaxf(fmaf(z0, wz0, a[0]) + b0, 0.f);
                    float v01 = fmaxf(fmaf(z0, wz1, a[1]) + b1, 0.f);
                    float v10 = fmaxf(fmaf(z1, wz0, a[2]) + b0, 0.f);
                    float v11 = fmaxf(fmaf(z1, wz1, a[3]) + b1, 0.f);
                    af[mt][kb][2 * t]     = packbf(v00, v01);
                    af[mt][kb][2 * t + 1] = packbf(v10, v11);
                }
            }
        }

        // ---- GEMM2: [32x128] = h1(regs) @ Ws1^T(smem) ----
#pragma unroll
        for (int mt = 0; mt < 2; mt++)
#pragma unroll
            for (int nt = 0; nt < 16; nt++) {
                acc[mt][nt][0] = 0.f; acc[mt][nt][1] = 0.f;
                acc[mt][nt][2] = 0.f; acc[mt][nt][3] = 0.f;
            }
#pragma unroll
        for (int kb = 0; kb < 8; kb++) {
            unsigned brow = (unsigned)kb * 16u + klane;
#pragma unroll
            for (int ntp = 0; ntp < 8; ntp++) {
                unsigned b0, b1, b2, b3;
                unsigned baddr = sbase + OFF_W1 + (unsigned)(ntp >> 2) * 16384u +
                                 swz(brow * 128u + (unsigned)(ntp & 3) * 32u + half16);
                ldsm4t(baddr, b0, b1, b2, b3);
#pragma unroll
                for (int mt = 0; mt < 2; mt++) {
                    mma16816(acc[mt][2 * ntp],     af[mt][kb][0], af[mt][kb][1],
                             af[mt][kb][2], af[mt][kb][3], b0, b1);
                    mma16816(acc[mt][2 * ntp + 1], af[mt][kb][0], af[mt][kb][1],
                             af[mt][kb][2], af[mt][kb][3], b2, b3);
                }
            }
        }
        // epilogue 2: relu(acc + bs1) -> A-fragments
#pragma unroll
        for (int mt = 0; mt < 2; mt++) {
#pragma unroll
            for (int kb = 0; kb < 8; kb++) {
#pragma unroll
                for (int t = 0; t < 2; t++) {
                    float *a = acc[mt][2 * kb + t];
                    int c0 = (2 * kb + t) * 8 + 2 * (lane & 3);
                    float b0 = sB1[c0], b1 = sB1[c0 + 1];
                    af[mt][kb][2 * t]     = packbf(fmaxf(a[0] + b0, 0.f),
                                                   fmaxf(a[1] + b1, 0.f));
                    af[mt][kb][2 * t + 1] = packbf(fmaxf(a[2] + b0, 0.f),
                                                   fmaxf(a[3] + b1, 0.f));
                }
            }
        }

        // ---- GEMM3: [32x128] = h2(regs) @ Ws2^T(smem) ----
#pragma unroll
        for (int mt = 0; mt < 2; mt++)
#pragma unroll
            for (int nt = 0; nt < 16; nt++) {
                acc[mt][nt][0] = 0.f; acc[mt][nt][1] = 0.f;
                acc[mt][nt][2] = 0.f; acc[mt][nt][3] = 0.f;
            }
#pragma unroll
        for (int kb = 0; kb < 8; kb++) {
            unsigned brow = (unsigned)kb * 16u + klane;
#pragma unroll
            for (int ntp = 0; ntp < 8; ntp++) {
                unsigned b0, b1, b2, b3;
                unsigned baddr = sbase + OFF_W2 + (unsigned)(ntp >> 2) * 16384u +
                                 swz(brow * 128u + (unsigned)(ntp & 3) * 32u + half16);
                ldsm4t(baddr, b0, b1, b2, b3);
#pragma unroll
                for (int mt = 0; mt < 2; mt++) {
                    mma16816(acc[mt][2 * ntp],     af[mt][kb][0], af[mt][kb][1],
                             af[mt][kb][2], af[mt][kb][3], b0, b1);
                    mma16816(acc[mt][2 * ntp + 1], af[mt][kb][0], af[mt][kb][1],
                             af[mt][kb][2], af[mt][kb][3], b2, b3);
                }
            }
        }
        // head: p = relu(acc + bs2) . wf  -> sigmoid -> out + X column
#pragma unroll
        for (int mt = 0; mt < 2; mt++) {
            const int r0 = mb + mt * 16 + (lane >> 2), r1 = r0 + 8;
            float p0 = 0.f, p1 = 0.f;
#pragma unroll
            for (int nt = 0; nt < 16; nt++) {
                float *a = acc[mt][nt];
                int c0 = nt * 8 + 2 * (lane & 3);
                float b0 = sB2[c0], b1 = sB2[c0 + 1];
                float w0 = sWf[c0], w1 = sWf[c0 + 1];
                p0 += fmaxf(a[0] + b0, 0.f) * w0 + fmaxf(a[1] + b1, 0.f) * w1;
                p1 += fmaxf(a[2] + b0, 0.f) * w0 + fmaxf(a[3] + b1, 0.f) * w1;
            }
            p0 += __shfl_xor_sync(0xffffffffu, p0, 1);
            p0 += __shfl_xor_sync(0xffffffffu, p0, 2);
            p1 += __shfl_xor_sync(0xffffffffu, p1, 1);
            p1 += __shfl_xor_sync(0xffffffffu, p1, 2);
            if ((lane & 3) == 0) {
                float bfi = sBF[i];
                float o0 = 1.f / (1.f + __expf(-(p0 + bfi)));
                float o1 = 1.f / (1.f + __expf(-(p1 + bfi)));
                out[(size_t)(R0 + r0) * XD + i] = o0;
                out[(size_t)(R0 + r1) * XD + i] = o1;
                *(__nv_bfloat16 *)(smem + OFF_X + swz((unsigned)(r0 * 128 + i * 2))) =
                    __float2bfloat16(o0);
                *(__nv_bfloat16 *)(smem + OFF_X + swz((unsigned)(r1 * 128 + i * 2))) =
                    __float2bfloat16(o1);
            }
        }
        // next-iteration __syncthreads publishes the X column
    }
}

// ---- prep: fold adjacency mask into per-step bf16 input weights ----
__global__ void prep_A_kernel(const float *__restrict__ M, const float *__restrict__ Wi) {
    int idx = blockIdx.x * blockDim.x + threadIdx.x;
    if (idx >= XD * XD * HD) return;
    int i = idx >> 13;
    int k = (idx >> 7) & 63;
    int n = idx & 127;
    float v = (k == i) ? 0.f : M[k * XD + i] * Wi[((size_t)i * HD + n) * (XD + 1) + k];
    g_A[idx] = __float2bfloat16(v);
}

// ---- prep: transpose shared weights to [k][n] bf16 ----
__global__ void prep_W_kernel(const float *__restrict__ Ws1, const float *__restrict__ Ws2) {
    int idx = blockIdx.x * blockDim.x + threadIdx.x;
    if (idx >= HD * HD) return;
    int k = idx >> 7, n = idx & 127;
    g_W1[idx] = __float2bfloat16(Ws1[n * HD + k]);
    g_W2[idx] = __float2bfloat16(Ws2[n * HD + k]);
}

extern "C" void kernel_launch(void *const *d_in, const int *in_sizes, int n_in,
                              void *d_out, int out_size) {
    const float *x   = (const float *)d_in[0];
    const float *z   = (const float *)d_in[1];
    const float *M   = (const float *)d_in[2];
    const float *Wi  = (const float *)d_in[3];
    const float *bi  = (const float *)d_in[4];
    const float *Ws1 = (const float *)d_in[5];
    const float *bs1 = (const float *)d_in[6];
    const float *Ws2 = (const float *)d_in[7];
    const float *bs2 = (const float *)d_in[8];
    const float *wf  = (const float *)d_in[9];
    const float *bf  = (const float *)d_in[10];
    float *out = (float *)d_out;

    cudaFuncSetAttribute(gen_kernel, cudaFuncAttributeMaxDynamicSharedMemorySize,
                         (int)SMEM_BYTES);

    prep_A_kernel<<<(XD * XD * HD + 255) / 256, 256>>>(M, Wi);
    prep_W_kernel<<<(HD * HD + 255) / 256, 256>>>(Ws1, Ws2);
    gen_kernel<<<BB / BM, NT, SMEM_BYTES>>>(x, z, Wi, bi, bs1, bs2, wf, bf, out);
}